// round 12
// baseline (speedup 1.0000x reference)
#include <cuda_runtime.h>
#include <cuda_bf16.h>
#include <math.h>
#include <stdint.h>

// Problem dims
#define BSZ 2
#define SEQ 512
#define HID 1024
#define NHD 16
#define HDD 64
#define NL  4
#define FFD 4096
#define NCL 14
#define TOK (BSZ*SEQ)          // 1024
#define SHs (SEQ*HID)          // 524288
#define HSC (SEQ*SEQ)          // 262144

// packed-weight layout (u32 units)
#define WPL   6291456ll        // per-layer u32: 4x(1024*512) + 4096*512 + 1024*2048
#define OFF_WQ 0ll
#define OFF_WK 524288ll
#define OFF_WV 1048576ll
#define OFF_WO 1572864ll
#define OFF_W1 2097152ll
#define OFF_W2 4194304ll
#define OFF_WT 25165824ll
#define WHN   25690112ll

// ---------------- scratch (device globals: no cudaMalloc allowed) -------------
__device__ float g_x[TOK*HID];
__device__ float g_q[TOK*HID];
__device__ float g_k[TOK*HID];
__device__ float g_v[TOK*HID];
__device__ float g_rel[SEQ*HID];
__device__ float g_pk[SEQ*HID];
__device__ float g_pq[SEQ*HID];
__device__ float g_sc[BSZ*NHD*SEQ*SEQ];
__device__ float g_c2p[BSZ*NHD*SEQ*SEQ];
__device__ float g_p2c[BSZ*NHD*SEQ*SEQ];
__device__ float g_ctx[TOK*HID];
__device__ float g_ff[TOK*FFD];
__device__ int   g_idxm[SEQ*SEQ];
__device__ float g_nll[TOK];
// packed bf16 hi/lo weights ([N][K] transposed)
__device__ uint32_t g_wh[WHN];
__device__ uint32_t g_wl[WHN];
// packed bf16 hi/lo activations (row-major [tok][k])
__device__ uint32_t g_qh[TOK*HID/2], g_ql[TOK*HID/2];
__device__ uint32_t g_kh[TOK*HID/2], g_kl[TOK*HID/2];
__device__ uint32_t g_pkh[SEQ*HID/2], g_pkl[SEQ*HID/2];
__device__ uint32_t g_pqh[SEQ*HID/2], g_pql[SEQ*HID/2];

// ---------------- job descriptors ---------------------------------------------
struct JobF { const float* A; const uint32_t* Bh; const uint32_t* Bl;
              float* C; const float* bias; long M; };               // 48B
struct JobS { const float* A; const uint32_t* Bh; const uint32_t* Bl; float* C; }; // 32B
template<typename JOB, int NJ> struct JobsA { JOB j[NJ]; };
__device__ __forceinline__ const float* jbias(const JobF& j) { return j.bias; }
__device__ __forceinline__ const float* jbias(const JobS&)   { return nullptr; }
__device__ __forceinline__ long jM(const JobF& j) { return j.M; }
__device__ __forceinline__ long jM(const JobS&)   { return 512; }
// old-style job (ctx kernel)
struct JobDesc { const float* A; const float* B; float* C; const float* bias; int M; int pad; };
template<int NJ> struct JobsP { JobDesc j[NJ]; };
// transpose jobs
struct TJob { const float* W; long off; int K; int N; };
struct TJobs { TJob j[25]; };

// ---------------- helpers ------------------------------------------------------
__device__ __forceinline__ float blk_sum(float v, float* red) {
    #pragma unroll
    for (int o = 16; o; o >>= 1) v += __shfl_down_sync(0xffffffffu, v, o);
    int w = threadIdx.x >> 5, lane = threadIdx.x & 31;
    int nw = blockDim.x >> 5;
    __syncthreads();
    if (lane == 0) red[w] = v;
    __syncthreads();
    if (threadIdx.x == 0) { float s = 0.f; for (int i = 0; i < nw; i++) s += red[i]; red[0] = s; }
    __syncthreads();
    return red[0];
}

__device__ __forceinline__ void split2(float x0, float x1, uint32_t& h, uint32_t& l) {
    __nv_bfloat16 h0 = __float2bfloat16_rn(x0);
    __nv_bfloat16 h1 = __float2bfloat16_rn(x1);
    float r0 = x0 - __bfloat162float(h0);
    float r1 = x1 - __bfloat162float(h1);
    __nv_bfloat162 hp; hp.x = h0; hp.y = h1;
    __nv_bfloat162 lp; lp.x = __float2bfloat16_rn(r0); lp.y = __float2bfloat16_rn(r1);
    h = *(uint32_t*)&hp;
    l = *(uint32_t*)&lp;
}
__device__ __forceinline__ uint32_t pack_hi2(float x0, float x1) {
    __nv_bfloat162 hp; hp.x = __float2bfloat16_rn(x0); hp.y = __float2bfloat16_rn(x1);
    return *(uint32_t*)&hp;
}
__device__ __forceinline__ uint32_t pack_lo2(float x0, float x1) {
    __nv_bfloat16 h0 = __float2bfloat16_rn(x0);
    __nv_bfloat16 h1 = __float2bfloat16_rn(x1);
    __nv_bfloat162 lp;
    lp.x = __float2bfloat16_rn(x0 - __bfloat162float(h0));
    lp.y = __float2bfloat16_rn(x1 - __bfloat162float(h1));
    return *(uint32_t*)&lp;
}
__device__ __forceinline__ void mma_bf16(float* d, const uint32_t* a, const uint32_t* b) {
    asm volatile(
        "mma.sync.aligned.m16n8k16.row.col.f32.bf16.bf16.f32 "
        "{%0,%1,%2,%3}, {%4,%5,%6,%7}, {%8,%9}, {%0,%1,%2,%3};\n"
        : "+f"(d[0]), "+f"(d[1]), "+f"(d[2]), "+f"(d[3])
        : "r"(a[0]), "r"(a[1]), "r"(a[2]), "r"(a[3]), "r"(b[0]), "r"(b[1]));
}
__device__ __forceinline__ uint32_t smem_u32(const void* p) {
    uint32_t a;
    asm("{ .reg .u64 t; cvta.to.shared.u64 t, %1; cvt.u32.u64 %0, t; }" : "=r"(a) : "l"(p));
    return a;
}
__device__ __forceinline__ void ldsm4(uint32_t& r0, uint32_t& r1, uint32_t& r2, uint32_t& r3,
                                      uint32_t addr) {
    asm volatile("ldmatrix.sync.aligned.m8n8.x4.shared.b16 {%0,%1,%2,%3}, [%4];"
                 : "=r"(r0), "=r"(r1), "=r"(r2), "=r"(r3) : "r"(addr));
}

// ======== weight transpose + bf16 hi/lo split: W[K,N] -> GH/GL [N][K] =========
__global__ void tsplit_k(TJobs P, uint32_t* __restrict__ GH, uint32_t* __restrict__ GL)
{
    TJob j = P.j[blockIdx.y];
    int ktiles = j.K >> 6, ntiles = j.N >> 5;
    int tile = blockIdx.x;
    if (tile >= ktiles * ntiles) return;
    int tk = tile % ktiles, tn = tile / ktiles;
    int k0 = tk << 6, nn0 = tn << 5;
    __shared__ float sm[64][33];
    for (int i = threadIdx.x; i < 2048; i += 256) {
        int r = i >> 5, c = i & 31;
        sm[r][c] = j.W[(long)(k0 + r) * j.N + nn0 + c];
    }
    __syncthreads();
    int Ku = j.K >> 1;
    for (int i = threadIdx.x; i < 1024; i += 256) {
        int kp = i & 31, n = i >> 5;
        float f0 = sm[2*kp][n], f1 = sm[2*kp+1][n];
        long o = j.off + (long)(nn0 + n) * Ku + (k0 >> 1) + kp;
        GH[o] = pack_hi2(f0, f1);
        GL[o] = pack_lo2(f0, f1);
    }
}

// ======== activation bf16 hi/lo split ==========================================
__global__ void asplit_k(const float* __restrict__ s, uint32_t* __restrict__ dh,
                         uint32_t* __restrict__ dl, int npairs)
{
    int i = blockIdx.x * 256 + threadIdx.x;
    if (i < npairs) {
        float2 v = ((const float2*)s)[i];
        dh[i] = pack_hi2(v.x, v.y);
        dl[i] = pack_lo2(v.x, v.y);
    }
}

// ======== ldmatrix-fed bf16 GEMM (3-term compensated) ==========================
// C = act(A @ B^T + bias), A fp32 [M,lda], Bh/Bl packed bf16 [N][K] (u32 stride ldbu).
// Block 128x64, BK=16, 8 warps (4x2), warp tile 32x32, double-buffered smem.
template<int ACT, typename JOB, int NJ>
__global__ __launch_bounds__(256)
void bgemm2_k(JobsA<JOB, NJ> P, int K, int lda, int ldbu, int ldc)
{
    const JOB jd = P.j[blockIdx.z];
    const int m0 = blockIdx.y << 7;
    if (m0 >= jM(jd)) return;
    const int n0 = blockIdx.x << 6;
    const float* __restrict__ A = jd.A;
    const uint32_t* __restrict__ Bh = jd.Bh;
    const uint32_t* __restrict__ Bl = jd.Bl;
    float* __restrict__ C = jd.C;
    const float* bias = jbias(jd);

    __shared__ uint32_t AhS[2][128][12];
    __shared__ uint32_t AlS[2][128][12];
    __shared__ uint32_t BhS[2][64][12];
    __shared__ uint32_t BlS[2][64][12];

    const int tid = threadIdx.x;
    const int lane = tid & 31, warp = tid >> 5;
    const int wm = warp >> 1, wn = warp & 1;
    const int t = lane & 3, g = lane >> 2;

    const int ar  = tid >> 1;           // A stage row
    const int acf = (tid & 1) << 3;     // A stage float col (0/8)
    const int brn = tid >> 2;           // B stage row
    const int bkq = (tid & 3) << 1;     // B stage u32 col (0,2,4,6)

    // ldmatrix lane addressing (bytes)
    const uint32_t aHb = smem_u32(&AhS[0][0][0]);
    const uint32_t aLb = smem_u32(&AlS[0][0][0]);
    const uint32_t bHb = smem_u32(&BhS[0][0][0]);
    const uint32_t bLb = smem_u32(&BlS[0][0][0]);
    const int aRow = ((lane >> 3) & 1) * 8 + (lane & 7);
    const int aCo  = (lane >> 4) * 16;
    const uint32_t aOff0 = (uint32_t)((wm*32 + aRow) * 48 + aCo);
    const uint32_t aOff1 = (uint32_t)((wm*32 + 16 + aRow) * 48 + aCo);
    const int bRow = (lane >> 4) * 8 + (lane & 7);
    const int bCo  = ((lane >> 3) & 1) * 16;
    const uint32_t bOff0 = (uint32_t)((wn*32 + bRow) * 48 + bCo);
    const uint32_t bOff1 = (uint32_t)((wn*32 + 16 + bRow) * 48 + bCo);

    float acc[2][4][4] = {};
    float4 ra0, ra1;
    uint2 rbh, rbl;

    // ---- prologue: k-tile 0 ----
    {
        const float* Ap = A + (long)(m0 + ar) * lda + acf;
        ra0 = *(const float4*)Ap; ra1 = *(const float4*)(Ap + 4);
        const long bo = (long)(n0 + brn) * ldbu + bkq;
        rbh = *(const uint2*)(Bh + bo);
        rbl = *(const uint2*)(Bl + bo);
    }
    {
        uint4 h4, l4;
        split2(ra0.x, ra0.y, h4.x, l4.x); split2(ra0.z, ra0.w, h4.y, l4.y);
        split2(ra1.x, ra1.y, h4.z, l4.z); split2(ra1.z, ra1.w, h4.w, l4.w);
        *(uint4*)&AhS[0][ar][acf >> 1] = h4;
        *(uint4*)&AlS[0][ar][acf >> 1] = l4;
        *(uint2*)&BhS[0][brn][bkq] = rbh;
        *(uint2*)&BlS[0][brn][bkq] = rbl;
    }
    __syncthreads();

    const int KT = K >> 4;
    for (int kt = 0; kt < KT; kt++) {
        const int s = kt & 1;
        const bool more = (kt + 1 < KT);
        if (more) {
            const int kf = (kt + 1) << 4;
            const float* Ap = A + (long)(m0 + ar) * lda + kf + acf;
            ra0 = *(const float4*)Ap; ra1 = *(const float4*)(Ap + 4);
            const long bo = (long)(n0 + brn) * ldbu + (kf >> 1) + bkq;
            rbh = *(const uint2*)(Bh + bo);
            rbl = *(const uint2*)(Bl + bo);
        }
        // ---- fragments via ldmatrix ----
        const uint32_t sA = (uint32_t)s * 6144u;
        const uint32_t sB = (uint32_t)s * 3072u;
        uint32_t ah[2][4], al[2][4], bh[4][2], bl[4][2];
        ldsm4(ah[0][0], ah[0][1], ah[0][2], ah[0][3], aHb + sA + aOff0);
        ldsm4(ah[1][0], ah[1][1], ah[1][2], ah[1][3], aHb + sA + aOff1);
        ldsm4(al[0][0], al[0][1], al[0][2], al[0][3], aLb + sA + aOff0);
        ldsm4(al[1][0], al[1][1], al[1][2], al[1][3], aLb + sA + aOff1);
        ldsm4(bh[0][0], bh[0][1], bh[1][0], bh[1][1], bHb + sB + bOff0);
        ldsm4(bh[2][0], bh[2][1], bh[3][0], bh[3][1], bHb + sB + bOff1);
        ldsm4(bl[0][0], bl[0][1], bl[1][0], bl[1][1], bLb + sB + bOff0);
        ldsm4(bl[2][0], bl[2][1], bl[3][0], bl[3][1], bLb + sB + bOff1);
        #pragma unroll
        for (int mt = 0; mt < 2; mt++)
            #pragma unroll
            for (int nt = 0; nt < 4; nt++) mma_bf16(acc[mt][nt], ah[mt], bh[nt]);
        #pragma unroll
        for (int mt = 0; mt < 2; mt++)
            #pragma unroll
            for (int nt = 0; nt < 4; nt++) mma_bf16(acc[mt][nt], ah[mt], bl[nt]);
        #pragma unroll
        for (int mt = 0; mt < 2; mt++)
            #pragma unroll
            for (int nt = 0; nt < 4; nt++) mma_bf16(acc[mt][nt], al[mt], bh[nt]);
        if (more) {
            const int s2 = (kt + 1) & 1;
            uint4 h4, l4;
            split2(ra0.x, ra0.y, h4.x, l4.x); split2(ra0.z, ra0.w, h4.y, l4.y);
            split2(ra1.x, ra1.y, h4.z, l4.z); split2(ra1.z, ra1.w, h4.w, l4.w);
            *(uint4*)&AhS[s2][ar][acf >> 1] = h4;
            *(uint4*)&AlS[s2][ar][acf >> 1] = l4;
            *(uint2*)&BhS[s2][brn][bkq] = rbh;
            *(uint2*)&BlS[s2][brn][bkq] = rbl;
        }
        __syncthreads();
    }

    // epilogue
    #pragma unroll
    for (int mt = 0; mt < 2; mt++) {
        #pragma unroll
        for (int nt = 0; nt < 4; nt++) {
            int col = n0 + (wn << 5) + (nt << 3) + (t << 1);
            float b0 = bias ? bias[col]     : 0.f;
            float b1 = bias ? bias[col + 1] : 0.f;
            #pragma unroll
            for (int half = 0; half < 2; half++) {
                int row = m0 + (wm << 5) + (mt << 4) + g + (half << 3);
                float v0 = acc[mt][nt][half * 2 + 0] + b0;
                float v1 = acc[mt][nt][half * 2 + 1] + b1;
                if (ACT == 1) {
                    v0 = 0.5f * v0 * (1.0f + erff(v0 * 0.70710678118654752f));
                    v1 = 0.5f * v1 * (1.0f + erff(v1 * 0.70710678118654752f));
                }
                *(float2*)(C + (long)row * ldc + col) = make_float2(v0, v1);
            }
        }
    }
}

// ======== 128x64 bf16 GEMM (ctx only; in-kernel split, scalar LDS) ============
template<int ACT, bool TB, int NJ>
__global__ __launch_bounds__(256)
void bgemm_k(JobsP<NJ> P, int K, int lda, int ldb, int ldc)
{
    const JobDesc jd = P.j[blockIdx.z];
    const int m0 = blockIdx.y << 7;
    if (m0 >= jd.M) return;
    const float* __restrict__ A  = jd.A;
    const float* __restrict__ Bm = jd.B;
    float* __restrict__ C = jd.C;
    const float* bias = jd.bias;
    const int n0 = blockIdx.x << 6;

    __shared__ uint32_t AhS[2][128][12];
    __shared__ uint32_t AlS[2][128][12];
    __shared__ uint32_t BhS[2][64][12];
    __shared__ uint32_t BlS[2][64][12];

    const int tid  = threadIdx.x;
    const int warp = tid >> 5, lane = tid & 31;
    const int wm = warp >> 1;
    const int wn = warp & 1;
    const int g  = lane >> 2;
    const int t  = lane & 3;

    const int ar  = tid >> 1;
    const int acf = (tid & 1) << 3;
    const int brn  = tid >> 2;
    const int bckf = (tid & 3) << 2;
    const int w8   = warp;
    const int ng   = lane & 15;
    const int isLo = lane >> 4;

    float acc[2][4][4] = {};
    float4 ra0, ra1, rb0, rb1;

    {
        const float* Ap = A + (long)(m0 + ar) * lda + acf;
        ra0 = *(const float4*)Ap; ra1 = *(const float4*)(Ap + 4);
        if (TB) {
            rb0 = *(const float4*)(Bm + (long)(n0 + brn) * ldb + bckf);
        } else {
            const float* Bp = Bm + (long)(2 * w8) * ldb + n0 + (ng << 2);
            rb0 = *(const float4*)Bp;
            rb1 = *(const float4*)(Bp + ldb);
        }
    }
    {
        uint4 h4, l4;
        split2(ra0.x, ra0.y, h4.x, l4.x); split2(ra0.z, ra0.w, h4.y, l4.y);
        split2(ra1.x, ra1.y, h4.z, l4.z); split2(ra1.z, ra1.w, h4.w, l4.w);
        *(uint4*)&AhS[0][ar][acf >> 1] = h4;
        *(uint4*)&AlS[0][ar][acf >> 1] = l4;
        if (TB) {
            uint32_t h0, l0, h1, l1;
            split2(rb0.x, rb0.y, h0, l0); split2(rb0.z, rb0.w, h1, l1);
            *(uint2*)&BhS[0][brn][bckf >> 1] = make_uint2(h0, h1);
            *(uint2*)&BlS[0][brn][bckf >> 1] = make_uint2(l0, l1);
        } else {
            float v0[4] = {rb0.x, rb0.y, rb0.z, rb0.w};
            float v1[4] = {rb1.x, rb1.y, rb1.z, rb1.w};
            int sw = w8 ^ ((ng & 3) << 1);
            #pragma unroll
            for (int j = 0; j < 4; j++) {
                int n = (ng << 2) + j;
                if (isLo) BlS[0][n][sw] = pack_lo2(v0[j], v1[j]);
                else      BhS[0][n][sw] = pack_hi2(v0[j], v1[j]);
            }
        }
    }
    __syncthreads();

    const int KT = K >> 4;
    for (int kt = 0; kt < KT; kt++) {
        const int s = kt & 1;
        const bool more = (kt + 1 < KT);
        if (more) {
            int k0 = (kt + 1) << 4;
            const float* Ap = A + (long)(m0 + ar) * lda + k0 + acf;
            ra0 = *(const float4*)Ap; ra1 = *(const float4*)(Ap + 4);
            if (TB) {
                rb0 = *(const float4*)(Bm + (long)(n0 + brn) * ldb + k0 + bckf);
            } else {
                const float* Bp = Bm + (long)(k0 + 2 * w8) * ldb + n0 + (ng << 2);
                rb0 = *(const float4*)Bp;
                rb1 = *(const float4*)(Bp + ldb);
            }
        }
        {
            uint32_t ah[2][4], al[2][4], bh[4][2], bl[4][2];
            #pragma unroll
            for (int mt = 0; mt < 2; mt++) {
                int mr = (wm << 5) + (mt << 4);
                ah[mt][0] = AhS[s][mr + g][t];
                ah[mt][1] = AhS[s][mr + g + 8][t];
                ah[mt][2] = AhS[s][mr + g][t + 4];
                ah[mt][3] = AhS[s][mr + g + 8][t + 4];
                al[mt][0] = AlS[s][mr + g][t];
                al[mt][1] = AlS[s][mr + g + 8][t];
                al[mt][2] = AlS[s][mr + g][t + 4];
                al[mt][3] = AlS[s][mr + g + 8][t + 4];
            }
            #pragma unroll
            for (int nt = 0; nt < 4; nt++) {
                int nc = (wn << 5) + (nt << 3) + g;
                int idx0 = TB ? t : (t ^ (((nc >> 2) & 3) << 1));
                bh[nt][0] = BhS[s][nc][idx0];
                bh[nt][1] = BhS[s][nc][idx0 ^ 4];
                bl[nt][0] = BlS[s][nc][idx0];
                bl[nt][1] = BlS[s][nc][idx0 ^ 4];
            }
            #pragma unroll
            for (int mt = 0; mt < 2; mt++)
                #pragma unroll
                for (int nt = 0; nt < 4; nt++) mma_bf16(acc[mt][nt], ah[mt], bh[nt]);
            #pragma unroll
            for (int mt = 0; mt < 2; mt++)
                #pragma unroll
                for (int nt = 0; nt < 4; nt++) mma_bf16(acc[mt][nt], ah[mt], bl[nt]);
            #pragma unroll
            for (int mt = 0; mt < 2; mt++)
                #pragma unroll
                for (int nt = 0; nt < 4; nt++) mma_bf16(acc[mt][nt], al[mt], bh[nt]);
        }
        if (more) {
            const int s2 = (kt + 1) & 1;
            uint4 h4, l4;
            split2(ra0.x, ra0.y, h4.x, l4.x); split2(ra0.z, ra0.w, h4.y, l4.y);
            split2(ra1.x, ra1.y, h4.z, l4.z); split2(ra1.z, ra1.w, h4.w, l4.w);
            *(uint4*)&AhS[s2][ar][acf >> 1] = h4;
            *(uint4*)&AlS[s2][ar][acf >> 1] = l4;
            if (TB) {
                uint32_t h0, l0, h1, l1;
                split2(rb0.x, rb0.y, h0, l0); split2(rb0.z, rb0.w, h1, l1);
                *(uint2*)&BhS[s2][brn][bckf >> 1] = make_uint2(h0, h1);
                *(uint2*)&BlS[s2][brn][bckf >> 1] = make_uint2(l0, l1);
            } else {
                float v0[4] = {rb0.x, rb0.y, rb0.z, rb0.w};
                float v1[4] = {rb1.x, rb1.y, rb1.z, rb1.w};
                int sw = w8 ^ ((ng & 3) << 1);
                #pragma unroll
                for (int j = 0; j < 4; j++) {
                    int n = (ng << 2) + j;
                    if (isLo) BlS[s2][n][sw] = pack_lo2(v0[j], v1[j]);
                    else      BhS[s2][n][sw] = pack_hi2(v0[j], v1[j]);
                }
            }
        }
        __syncthreads();
    }

    #pragma unroll
    for (int mt = 0; mt < 2; mt++) {
        #pragma unroll
        for (int nt = 0; nt < 4; nt++) {
            int col = n0 + (wn << 5) + (nt << 3) + (t << 1);
            float b0 = bias ? bias[col]     : 0.f;
            float b1 = bias ? bias[col + 1] : 0.f;
            #pragma unroll
            for (int half = 0; half < 2; half++) {
                int row = m0 + (wm << 5) + (mt << 4) + g + (half << 3);
                float v0 = acc[mt][nt][half * 2 + 0] + b0;
                float v1 = acc[mt][nt][half * 2 + 1] + b1;
                if (ACT == 1) {
                    v0 = 0.5f * v0 * (1.0f + erff(v0 * 0.70710678118654752f));
                    v1 = 0.5f * v1 * (1.0f + erff(v1 * 0.70710678118654752f));
                }
                *(float2*)(C + (long)row * ldc + col) = make_float2(v0, v1);
            }
        }
    }
}

// ---------------- embedding: x = LN(word_emb[id]) * maskf ---------------------
__global__ void embed_ln_k(const float* __restrict__ emb,
                           const float* __restrict__ s, const float* __restrict__ b,
                           const int* __restrict__ ids, const int* __restrict__ am,
                           float* __restrict__ out)
{
    __shared__ float sh[HID];
    __shared__ float red[8];
    int tok = blockIdx.x;
    long ebase = (long)ids[tok] * HID;
    float m = (float)am[tok];
    float ls = 0.f;
    for (int i = threadIdx.x; i < HID; i += blockDim.x) { float v = emb[ebase + i]; sh[i] = v; ls += v; }
    __syncthreads();
    float mu = blk_sum(ls, red) * (1.0f / HID);
    float lv = 0.f;
    for (int i = threadIdx.x; i < HID; i += blockDim.x) { float d = sh[i] - mu; lv += d * d; }
    float var = blk_sum(lv, red) * (1.0f / HID);
    float r = rsqrtf(var + 1e-7f);
    long obase = (long)tok * HID;
    for (int i = threadIdx.x; i < HID; i += blockDim.x)
        out[obase + i] = ((sh[i] - mu) * r * s[i] + b[i]) * m;
}

// ---------------- residual + LN -----------------------------------------------
__global__ void add_ln_k(const float* res, const float* __restrict__ t,
                         const float* __restrict__ s, const float* __restrict__ b,
                         float* out)
{
    __shared__ float sh[HID];
    __shared__ float red[8];
    long base = (long)blockIdx.x * HID;
    float ls = 0.f;
    for (int i = threadIdx.x; i < HID; i += blockDim.x) {
        float v = t[base + i];
        if (res) v += res[base + i];
        sh[i] = v; ls += v;
    }
    __syncthreads();
    float mu = blk_sum(ls, red) * (1.0f / HID);
    float lv = 0.f;
    for (int i = threadIdx.x; i < HID; i += blockDim.x) { float d = sh[i] - mu; lv += d * d; }
    float var = blk_sum(lv, red) * (1.0f / HID);
    float r = rsqrtf(var + 1e-7f);
    for (int i = threadIdx.x; i < HID; i += blockDim.x)
        out[base + i] = (sh[i] - mu) * r * s[i] + b[i];
}

// ---------------- DeBERTa log-bucket relative index ---------------------------
__global__ void build_idx_k(int* __restrict__ idxm)
{
    int q = blockIdx.x;
    const int mid = 128;
    for (int k = threadIdx.x; k < SEQ; k += blockDim.x) {
        int rel = q - k;
        int a = (rel < mid && rel > -mid) ? (mid - 1) : (rel < 0 ? -rel : rel);
        int bucket;
        if (a <= mid) bucket = rel;
        else {
            float lp = ceilf(logf((float)a / (float)mid) / logf(511.0f / (float)mid) * (float)(mid - 1))
                       + (float)mid;
            float sgn = (rel > 0) ? 1.f : ((rel < 0) ? -1.f : 0.f);
            bucket = (int)(lp * sgn);
        }
        int J = bucket + 256;
        J = J < 0 ? 0 : (J > 511 ? 511 : J);
        idxm[q * SEQ + k] = J;
    }
}

// ------- combine + mask + softmax ---------------------------------------------
__global__ void attn_softmax_k(float* __restrict__ sc, const float* __restrict__ c2p,
                               const float* __restrict__ p2c, const int* __restrict__ idxm,
                               const int* __restrict__ am)
{
    __shared__ float red[4];
    int q = blockIdx.x, z = blockIdx.y;
    int b = z >> 4;
    long ro = ((long)z * SEQ + q) * (long)SEQ;
    float* row = sc + ro;
    const float* cr = c2p + ro;
    const float* pb = p2c + (long)z * SEQ * 512;
    int mq = am[b * SEQ + q];
    const float scale = sqrtf(3.0f * (float)HDD);
    float vals[4]; int msk[4];
    float mx = -3.402823466e38f;
    #pragma unroll
    for (int t = 0; t < 4; t++) {
        int k = threadIdx.x + t * 128;
        int J = idxm[q * SEQ + k];
        float v = (row[k] + cr[J] + pb[(long)k * 512 + J]) / scale;
        int mk = mq & am[b * SEQ + k];
        vals[t] = v; msk[t] = mk;
        if (mk) mx = fmaxf(mx, v);
    }
    #pragma unroll
    for (int o = 16; o; o >>= 1) mx = fmaxf(mx, __shfl_down_sync(0xffffffffu, mx, o));
    if ((threadIdx.x & 31) == 0) red[threadIdx.x >> 5] = mx;
    __syncthreads();
    mx = fmaxf(fmaxf(red[0], red[1]), fmaxf(red[2], red[3]));
    float ls = 0.f;
    #pragma unroll
    for (int t = 0; t < 4; t++) {
        float e = msk[t] ? expf(vals[t] - mx) : 0.f;
        vals[t] = e; ls += e;
    }
    __syncthreads();
    #pragma unroll
    for (int o = 16; o; o >>= 1) ls += __shfl_down_sync(0xffffffffu, ls, o);
    if ((threadIdx.x & 31) == 0) red[threadIdx.x >> 5] = ls;
    __syncthreads();
    float sum = red[0] + red[1] + red[2] + red[3];
    float inv = sum > 0.f ? 1.0f / sum : 0.f;
    #pragma unroll
    for (int t = 0; t < 4; t++) row[threadIdx.x + t * 128] = vals[t] * inv;
}

// ---------------- decoder (N=14) + per-row masked NLL -------------------------
__global__ void decoder_k(const float* __restrict__ t, const float* __restrict__ Wd,
                          const float* __restrict__ bd, const int* __restrict__ labels,
                          const int* __restrict__ am, float* __restrict__ out,
                          int logit_limit, float* __restrict__ nll)
{
    __shared__ float sh[HID];
    __shared__ float wred[4][NCL];
    __shared__ float lg[NCL];
    int row = blockIdx.x;
    long base = (long)row * HID;
    for (int i = threadIdx.x; i < HID; i += 128) sh[i] = t[base + i];
    __syncthreads();
    float p[NCL];
    #pragma unroll
    for (int c = 0; c < NCL; c++) p[c] = 0.f;
    for (int i = threadIdx.x; i < HID; i += 128) {
        float tv = sh[i];
        const float* w = Wd + (long)i * NCL;
        #pragma unroll
        for (int c = 0; c < NCL; c++) p[c] = fmaf(tv, w[c], p[c]);
    }
    #pragma unroll
    for (int c = 0; c < NCL; c++)
        #pragma unroll
        for (int o = 16; o; o >>= 1) p[c] += __shfl_down_sync(0xffffffffu, p[c], o);
    if ((threadIdx.x & 31) == 0) {
        int w = threadIdx.x >> 5;
        #pragma unroll
        for (int c = 0; c < NCL; c++) wred[w][c] = p[c];
    }
    __syncthreads();
    if (threadIdx.x < NCL) {
        float v = wred[0][threadIdx.x] + wred[1][threadIdx.x]
                + wred[2][threadIdx.x] + wred[3][threadIdx.x] + bd[threadIdx.x];
        lg[threadIdx.x] = v;
        int oi = row * NCL + threadIdx.x;
        if (oi < logit_limit) out[oi] = v;
    }
    __syncthreads();
    if (threadIdx.x == 0) {
        float m = lg[0];
        #pragma unroll
        for (int c = 1; c < NCL; c++) m = fmaxf(m, lg[c]);
        float ssum = 0.f;
        #pragma unroll
        for (int c = 0; c < NCL; c++) ssum += expf(lg[c] - m);
        float lse = m + logf(ssum);
        float nl = lse - lg[labels[row]];
        nll[row] = nl * (float)am[row];
    }
}

__global__ void finalize_k(const float* __restrict__ nll, const int* __restrict__ am,
                           float* __restrict__ out, int loss_idx)
{
    __shared__ float red[8];
    float a = 0.f, bm = 0.f;
    for (int i = threadIdx.x; i < TOK; i += 256) { a += nll[i]; bm += (float)am[i]; }
    float sa = blk_sum(a, red);
    float sb = blk_sum(bm, red);
    if (threadIdx.x == 0 && loss_idx >= 0) out[loss_idx] = sa / fmaxf(sb, 1.0f);
}

// ------------------------------- host driver ----------------------------------
static inline JobDesc mkjob(const float* A, const float* B, float* C,
                            const float* bias, int M)
{
    JobDesc d; d.A = A; d.B = B; d.C = C; d.bias = bias; d.M = M; d.pad = 0;
    return d;
}
static inline JobF mkjf(const float* A, const uint32_t* Bh, const uint32_t* Bl,
                        float* C, const float* bias, long M)
{
    JobF d; d.A = A; d.Bh = Bh; d.Bl = Bl; d.C = C; d.bias = bias; d.M = M;
    return d;
}

extern "C" void kernel_launch(void* const* d_in, const int* in_sizes, int n_in,
                              void* d_out, int out_size)
{
    (void)in_sizes; (void)n_in;
    const float* word_emb = (const float*)d_in[0];
    const float* emb_ln_s = (const float*)d_in[1];
    const float* emb_ln_b = (const float*)d_in[2];
    const float* rel_emb  = (const float*)d_in[3];
    const float* rel_ln_s = (const float*)d_in[4];
    const float* rel_ln_b = (const float*)d_in[5];
    const float* Wq = (const float*)d_in[6];
    const float* bq = (const float*)d_in[7];
    const float* Wk = (const float*)d_in[8];
    const float* bk = (const float*)d_in[9];
    const float* Wv = (const float*)d_in[10];
    const float* bv = (const float*)d_in[11];
    const float* Wo = (const float*)d_in[12];
    const float* bo = (const float*)d_in[13];
    const float* ln1_s = (const float*)d_in[14];
    const float* ln1_b = (const float*)d_in[15];
    const float* W1 = (const float*)d_in[16];
    const float* b1 = (const float*)d_in[17];
    const float* W2 = (const float*)d_in[18];
    const float* b2 = (const float*)d_in[19];
    const float* ln2_s = (const float*)d_in[20];
    const float* ln2_b = (const float*)d_in[21];
    const float* Wt = (const float*)d_in[22];
    const float* bt = (const float*)d_in[23];
    const float* tln_s = (const float*)d_in[24];
    const float* tln_b = (const float*)d_in[25];
    const float* Wd = (const float*)d_in[26];
    const float* bd = (const float*)d_in[27];
    const int* ids    = (const int*)d_in[28];
    const int* am     = (const int*)d_in[29];
    const int* labels = (const int*)d_in[30];
    float* out = (float*)d_out;

    float *x, *q, *k, *v, *rel, *pk, *pq, *sc, *c2p, *p2c, *ctx, *ff, *nll;
    int* idxm;
    uint32_t *wh, *wl, *qh, *ql, *kh, *kl, *pkh, *pkl, *pqh, *pql;
    cudaGetSymbolAddress((void**)&x,   g_x);
    cudaGetSymbolAddress((void**)&q,   g_q);
    cudaGetSymbolAddress((void**)&k,   g_k);
    cudaGetSymbolAddress((void**)&v,   g_v);
    cudaGetSymbolAddress((void**)&rel, g_rel);
    cudaGetSymbolAddress((void**)&pk,  g_pk);
    cudaGetSymbolAddress((void**)&pq,  g_pq);
    cudaGetSymbolAddress((void**)&sc,  g_sc);
    cudaGetSymbolAddress((void**)&c2p, g_c2p);
    cudaGetSymbolAddress((void**)&p2c, g_p2c);
    cudaGetSymbolAddress((void**)&ctx, g_ctx);
    cudaGetSymbolAddress((void**)&ff,  g_ff);
    cudaGetSymbolAddress((void**)&nll, g_nll);
    cudaGetSymbolAddress((void**)&idxm, g_idxm);
    cudaGetSymbolAddress((void**)&wh,  g_wh);
    cudaGetSymbolAddress((void**)&wl,  g_wl);
    cudaGetSymbolAddress((void**)&qh,  g_qh);  cudaGetSymbolAddress((void**)&ql, g_ql);
    cudaGetSymbolAddress((void**)&kh,  g_kh);  cudaGetSymbolAddress((void**)&kl, g_kl);
    cudaGetSymbolAddress((void**)&pkh, g_pkh); cudaGetSymbolAddress((void**)&pkl, g_pkl);
    cudaGetSymbolAddress((void**)&pqh, g_pqh); cudaGetSymbolAddress((void**)&pql, g_pql);

    // ---- weight transpose + split (all layers, one launch) ----
    TJobs tj;
    int nj = 0;
    for (int l = 0; l < NL; l++) {
        long lo = (long)l * WPL;
        tj.j[nj++] = TJob{Wq + (long)l*HID*HID, lo + OFF_WQ, HID, HID};
        tj.j[nj++] = TJob{Wk + (long)l*HID*HID, lo + OFF_WK, HID, HID};
        tj.j[nj++] = TJob{Wv + (long)l*HID*HID, lo + OFF_WV, HID, HID};
        tj.j[nj++] = TJob{Wo + (long)l*HID*HID, lo + OFF_WO, HID, HID};
        tj.j[nj++] = TJob{W1 + (long)l*HID*FFD, lo + OFF_W1, HID, FFD};
        tj.j[nj++] = TJob{W2 + (long)l*FFD*HID, lo + OFF_W2, FFD, HID};
    }
    tj.j[nj++] = TJob{Wt, OFF_WT, HID, HID};
    tsplit_k<<<dim3(2048, 25), 256>>>(tj, wh, wl);

    build_idx_k<<<SEQ, 128>>>(idxm);
    embed_ln_k<<<TOK, 256>>>(word_emb, emb_ln_s, emb_ln_b, ids, am, x);
    add_ln_k<<<SEQ, 256>>>(nullptr, rel_emb, rel_ln_s, rel_ln_b, rel);

    // ---- fixed score job table (bf16 activation B operands) ----
    JobsA<JobS, 96> scJobs;
    for (int job = 0; job < 3; job++)
        for (int head = 0; head < 32; head++) {
            int b = head >> 4, h = head & 15;
            const float* Aj = (job < 2 ? q : k) + (long)b * SHs + h * HDD;
            const uint32_t *Bhj, *Blj;
            if (job == 0)      { Bhj = kh + (long)b*SEQ*512 + h*32; Blj = kl + (long)b*SEQ*512 + h*32; }
            else if (job == 1) { Bhj = pkh + h*32; Blj = pkl + h*32; }
            else               { Bhj = pqh + h*32; Blj = pql + h*32; }
            float* Cj = (job == 0 ? sc : job == 1 ? c2p : p2c) + (long)head * HSC;
            scJobs.j[job * 32 + head] = JobS{Aj, Bhj, Blj, Cj};
        }
    JobsP<32> ctxJobs;
    for (int head = 0; head < 32; head++) {
        int b = head >> 4, h = head & 15;
        ctxJobs.j[head] = mkjob(sc + (long)head * HSC,
                                v + (long)b * SHs + h * HDD,
                                ctx + (long)b * SHs + h * HDD, nullptr, 512);
    }

    for (int l = 0; l < NL; l++) {
        long lo = (long)l * WPL;
        const float* bq_l = bq + l * HID;
        const float* bk_l = bk + l * HID;
        const float* bv_l = bv + l * HID;
        const float* bo_l = bo + l * HID;
        const float* b1_l = b1 + l * FFD;
        const float* b2_l = b2 + l * HID;

        // fused Q/K/V projections + positional K/Q (share_att_key)
        JobsA<JobF, 8> pj;
        pj.j[0] = mkjf(x,   wh + lo + OFF_WQ, wl + lo + OFF_WQ, q,  bq_l, 1024);
        pj.j[1] = mkjf(x,   wh + lo + OFF_WK, wl + lo + OFF_WK, k,  bk_l, 1024);
        pj.j[2] = mkjf(x,   wh + lo + OFF_WV, wl + lo + OFF_WV, v,  bv_l, 1024);
        pj.j[3] = mkjf(rel, wh + lo + OFF_WK, wl + lo + OFF_WK, pk, bk_l, 512);
        pj.j[4] = mkjf(rel, wh + lo + OFF_WQ, wl + lo + OFF_WQ, pq, bq_l, 512);
        bgemm2_k<0, JobF, 8><<<dim3(16, 8, 5), 256>>>(pj, HID, HID, 512, HID);

        // split k,q,pk,pq to bf16 hi/lo for score GEMMs
        asplit_k<<<2048, 256>>>(k,  kh,  kl,  TOK*HID/2);
        asplit_k<<<2048, 256>>>(pk, pkh, pkl, SEQ*HID/2);
        asplit_k<<<2048, 256>>>(pq, pqh, pql, SEQ*HID/2);

        // fused attention GEMMs: qk, c2p, p2c
        bgemm2_k<0, JobS, 96><<<dim3(8, 4, 96), 256>>>(scJobs, HDD, HID, 512, 512);

        // combine disentangled biases + mask + softmax
        attn_softmax_k<<<dim3(SEQ, BSZ * NHD), 128>>>(sc, c2p, p2c, idxm, am);

        // ctx = probs @ V (per head, N=64) — scalar-staged kernel
        bgemm_k<0, false, 32><<<dim3(1, 4, 32), 256>>>(ctxJobs, SEQ, 512, HID, HID);

        // output proj + residual LN
        JobsA<JobF, 8> oj;
        oj.j[0] = mkjf(ctx, wh + lo + OFF_WO, wl + lo + OFF_WO, ff, bo_l, 1024);
        bgemm2_k<0, JobF, 8><<<dim3(16, 8, 1), 256>>>(oj, HID, HID, 512, HID);
        add_ln_k<<<TOK, 256>>>(x, ff, ln1_s + l * HID, ln1_b + l * HID, x);

        // FFN
        JobsA<JobF, 8> f1;
        f1.j[0] = mkjf(x, wh + lo + OFF_W1, wl + lo + OFF_W1, ff, b1_l, 1024);
        bgemm2_k<1, JobF, 8><<<dim3(64, 8, 1), 256>>>(f1, HID, HID, 512, FFD);
        JobsA<JobF, 8> f2;
        f2.j[0] = mkjf(ff, wh + lo + OFF_W2, wl + lo + OFF_W2, ctx, b2_l, 1024);
        bgemm2_k<0, JobF, 8><<<dim3(16, 8, 1), 256>>>(f2, FFD, FFD, 2048, HID);
        add_ln_k<<<TOK, 256>>>(x, ctx, ln2_s + l * HID, ln2_b + l * HID, x);
    }

    // transform head: LN(gelu(x @ Wt + bt))
    JobsA<JobF, 8> thj;
    thj.j[0] = mkjf(x, wh + OFF_WT, wl + OFF_WT, ff, bt, 1024);
    bgemm2_k<1, JobF, 8><<<dim3(16, 8, 1), 256>>>(thj, HID, HID, 512, HID);
    add_ln_k<<<TOK, 256>>>(nullptr, ff, tln_s, tln_b, q);   // reuse q buffer as t

    int logits_n = TOK * NCL;                               // 14336
    int logit_limit = (out_size > 1) ? (out_size < logits_n ? out_size : logits_n) : 0;
    int loss_idx = (out_size == 1) ? 0 : (out_size > logits_n ? logits_n : -1);
    decoder_k<<<TOK, 128>>>(q, Wd, bd, labels, am, out, logit_limit, nll);
    finalize_k<<<1, 256>>>(nll, am, out, loss_idx);
}

// round 13
// speedup vs baseline: 1.1803x; 1.1803x over previous
#include <cuda_runtime.h>
#include <cuda_bf16.h>
#include <math.h>
#include <stdint.h>

// Problem dims
#define BSZ 2
#define SEQ 512
#define HID 1024
#define NHD 16
#define HDD 64
#define NL  4
#define FFD 4096
#define NCL 14
#define TOK (BSZ*SEQ)          // 1024
#define SHs (SEQ*HID)          // 524288
#define HSC (SEQ*SEQ)          // 262144

// ---------------- scratch (device globals: no cudaMalloc allowed) -------------
__device__ float g_x[TOK*HID];
__device__ float g_q[TOK*HID];
__device__ float g_k[TOK*HID];
__device__ float g_v[TOK*HID];
__device__ float g_rel[SEQ*HID];
__device__ float g_pk[SEQ*HID];
__device__ float g_pq[SEQ*HID];
__device__ float g_sc[BSZ*NHD*SEQ*SEQ];
__device__ float g_c2p[BSZ*NHD*SEQ*SEQ];
__device__ float g_p2c[BSZ*NHD*SEQ*SEQ];
__device__ float g_ctx[TOK*HID];
__device__ float g_ff[TOK*FFD];
__device__ int   g_idxm[SEQ*SEQ];
__device__ float g_nll[TOK];

// ---------------- job descriptors (passed in kernel params) -------------------
struct JobDesc { const float* A; const float* B; float* C; const float* bias; int M; int pad; };
template<int NJ> struct JobsP { JobDesc j[NJ]; };

// ---------------- block reduction helper --------------------------------------
__device__ __forceinline__ float blk_sum(float v, float* red) {
    #pragma unroll
    for (int o = 16; o; o >>= 1) v += __shfl_down_sync(0xffffffffu, v, o);
    int w = threadIdx.x >> 5, lane = threadIdx.x & 31;
    int nw = blockDim.x >> 5;
    __syncthreads();
    if (lane == 0) red[w] = v;
    __syncthreads();
    if (threadIdx.x == 0) { float s = 0.f; for (int i = 0; i < nw; i++) s += red[i]; red[0] = s; }
    __syncthreads();
    return red[0];
}

// ---------------- bf16 split helpers ------------------------------------------
__device__ __forceinline__ void split2(float x0, float x1, uint32_t& h, uint32_t& l) {
    __nv_bfloat16 h0 = __float2bfloat16_rn(x0);
    __nv_bfloat16 h1 = __float2bfloat16_rn(x1);
    float r0 = x0 - __bfloat162float(h0);
    float r1 = x1 - __bfloat162float(h1);
    __nv_bfloat162 hp; hp.x = h0; hp.y = h1;
    __nv_bfloat162 lp; lp.x = __float2bfloat16_rn(r0); lp.y = __float2bfloat16_rn(r1);
    h = *(uint32_t*)&hp;
    l = *(uint32_t*)&lp;
}
__device__ __forceinline__ uint32_t pack_hi2(float x0, float x1) {
    __nv_bfloat162 hp; hp.x = __float2bfloat16_rn(x0); hp.y = __float2bfloat16_rn(x1);
    return *(uint32_t*)&hp;
}
__device__ __forceinline__ uint32_t pack_lo2(float x0, float x1) {
    __nv_bfloat16 h0 = __float2bfloat16_rn(x0);
    __nv_bfloat16 h1 = __float2bfloat16_rn(x1);
    __nv_bfloat162 lp;
    lp.x = __float2bfloat16_rn(x0 - __bfloat162float(h0));
    lp.y = __float2bfloat16_rn(x1 - __bfloat162float(h1));
    return *(uint32_t*)&lp;
}

__device__ __forceinline__ void mma_bf16(float* d, const uint32_t* a, const uint32_t* b) {
    asm volatile(
        "mma.sync.aligned.m16n8k16.row.col.f32.bf16.bf16.f32 "
        "{%0,%1,%2,%3}, {%4,%5,%6,%7}, {%8,%9}, {%0,%1,%2,%3};\n"
        : "+f"(d[0]), "+f"(d[1]), "+f"(d[2]), "+f"(d[3])
        : "r"(a[0]), "r"(a[1]), "r"(a[2]), "r"(a[3]), "r"(b[0]), "r"(b[1]));
}

// ======== 128x64 bf16 tensor-core GEMM (3xBF16 compensated, 256 threads) ======
// Block tile 128(M) x 64(N), BK=16, 8 warps (4x2), warp tile 32x32.
// TB=true -> B given as [N,K] row-major (computes A @ B^T).
template<int ACT, bool TB, int NJ>
__global__ __launch_bounds__(256)
void bgemm_k(JobsP<NJ> P, int K, int lda, int ldb, int ldc)
{
    const JobDesc jd = P.j[blockIdx.z];
    const int m0 = blockIdx.y << 7;
    if (m0 >= jd.M) return;
    const float* __restrict__ A  = jd.A;
    const float* __restrict__ Bm = jd.B;
    float* __restrict__ C = jd.C;
    const float* bias = jd.bias;
    const int n0 = blockIdx.x << 6;

    __shared__ uint32_t AhS[2][128][12];
    __shared__ uint32_t AlS[2][128][12];
    __shared__ uint32_t BhS[2][64][12];
    __shared__ uint32_t BlS[2][64][12];

    const int tid  = threadIdx.x;
    const int warp = tid >> 5, lane = tid & 31;
    const int wm = warp >> 1;          // 0..3
    const int wn = warp & 1;           // 0..1
    const int g  = lane >> 2;          // 0..7
    const int t  = lane & 3;           // 0..3

    const int ar  = tid >> 1;                // 0..127
    const int acf = (tid & 1) << 3;          // 0 or 8
    const int brn  = tid >> 2;               // 0..63
    const int bckf = (tid & 3) << 2;         // 0,4,8,12
    const int w8   = warp;                   // 0..7 -> k pair
    const int ng   = lane & 15;              // n group (4 floats)
    const int isLo = lane >> 4;

    float acc[2][4][4] = {};
    float4 ra0, ra1, rb0, rb1;

    {
        const float* Ap = A + (long)(m0 + ar) * lda + acf;
        ra0 = *(const float4*)Ap; ra1 = *(const float4*)(Ap + 4);
        if (TB) {
            rb0 = *(const float4*)(Bm + (long)(n0 + brn) * ldb + bckf);
        } else {
            const float* Bp = Bm + (long)(2 * w8) * ldb + n0 + (ng << 2);
            rb0 = *(const float4*)Bp;
            rb1 = *(const float4*)(Bp + ldb);
        }
    }
    {
        uint4 h4, l4;
        split2(ra0.x, ra0.y, h4.x, l4.x); split2(ra0.z, ra0.w, h4.y, l4.y);
        split2(ra1.x, ra1.y, h4.z, l4.z); split2(ra1.z, ra1.w, h4.w, l4.w);
        *(uint4*)&AhS[0][ar][acf >> 1] = h4;
        *(uint4*)&AlS[0][ar][acf >> 1] = l4;
        if (TB) {
            uint32_t h0, l0, h1, l1;
            split2(rb0.x, rb0.y, h0, l0); split2(rb0.z, rb0.w, h1, l1);
            *(uint2*)&BhS[0][brn][bckf >> 1] = make_uint2(h0, h1);
            *(uint2*)&BlS[0][brn][bckf >> 1] = make_uint2(l0, l1);
        } else {
            float v0[4] = {rb0.x, rb0.y, rb0.z, rb0.w};
            float v1[4] = {rb1.x, rb1.y, rb1.z, rb1.w};
            int sw = w8 ^ ((ng & 3) << 1);
            #pragma unroll
            for (int j = 0; j < 4; j++) {
                int n = (ng << 2) + j;
                if (isLo) BlS[0][n][sw] = pack_lo2(v0[j], v1[j]);
                else      BhS[0][n][sw] = pack_hi2(v0[j], v1[j]);
            }
        }
    }
    __syncthreads();

    const int KT = K >> 4;
    for (int kt = 0; kt < KT; kt++) {
        const int s = kt & 1;
        const bool more = (kt + 1 < KT);
        if (more) {
            int k0 = (kt + 1) << 4;
            const float* Ap = A + (long)(m0 + ar) * lda + k0 + acf;
            ra0 = *(const float4*)Ap; ra1 = *(const float4*)(Ap + 4);
            if (TB) {
                rb0 = *(const float4*)(Bm + (long)(n0 + brn) * ldb + k0 + bckf);
            } else {
                const float* Bp = Bm + (long)(k0 + 2 * w8) * ldb + n0 + (ng << 2);
                rb0 = *(const float4*)Bp;
                rb1 = *(const float4*)(Bp + ldb);
            }
        }
        {
            uint32_t ah[2][4], al[2][4], bh[4][2], bl[4][2];
            #pragma unroll
            for (int mt = 0; mt < 2; mt++) {
                int mr = (wm << 5) + (mt << 4);
                ah[mt][0] = AhS[s][mr + g][t];
                ah[mt][1] = AhS[s][mr + g + 8][t];
                ah[mt][2] = AhS[s][mr + g][t + 4];
                ah[mt][3] = AhS[s][mr + g + 8][t + 4];
                al[mt][0] = AlS[s][mr + g][t];
                al[mt][1] = AlS[s][mr + g + 8][t];
                al[mt][2] = AlS[s][mr + g][t + 4];
                al[mt][3] = AlS[s][mr + g + 8][t + 4];
            }
            #pragma unroll
            for (int nt = 0; nt < 4; nt++) {
                int nc = (wn << 5) + (nt << 3) + g;
                int idx0 = TB ? t : (t ^ (((nc >> 2) & 3) << 1));
                bh[nt][0] = BhS[s][nc][idx0];
                bh[nt][1] = BhS[s][nc][idx0 ^ 4];
                bl[nt][0] = BlS[s][nc][idx0];
                bl[nt][1] = BlS[s][nc][idx0 ^ 4];
            }
            #pragma unroll
            for (int mt = 0; mt < 2; mt++)
                #pragma unroll
                for (int nt = 0; nt < 4; nt++) mma_bf16(acc[mt][nt], ah[mt], bh[nt]);
            #pragma unroll
            for (int mt = 0; mt < 2; mt++)
                #pragma unroll
                for (int nt = 0; nt < 4; nt++) mma_bf16(acc[mt][nt], ah[mt], bl[nt]);
            #pragma unroll
            for (int mt = 0; mt < 2; mt++)
                #pragma unroll
                for (int nt = 0; nt < 4; nt++) mma_bf16(acc[mt][nt], al[mt], bh[nt]);
        }
        if (more) {
            const int s2 = (kt + 1) & 1;
            uint4 h4, l4;
            split2(ra0.x, ra0.y, h4.x, l4.x); split2(ra0.z, ra0.w, h4.y, l4.y);
            split2(ra1.x, ra1.y, h4.z, l4.z); split2(ra1.z, ra1.w, h4.w, l4.w);
            *(uint4*)&AhS[s2][ar][acf >> 1] = h4;
            *(uint4*)&AlS[s2][ar][acf >> 1] = l4;
            if (TB) {
                uint32_t h0, l0, h1, l1;
                split2(rb0.x, rb0.y, h0, l0); split2(rb0.z, rb0.w, h1, l1);
                *(uint2*)&BhS[s2][brn][bckf >> 1] = make_uint2(h0, h1);
                *(uint2*)&BlS[s2][brn][bckf >> 1] = make_uint2(l0, l1);
            } else {
                float v0[4] = {rb0.x, rb0.y, rb0.z, rb0.w};
                float v1[4] = {rb1.x, rb1.y, rb1.z, rb1.w};
                int sw = w8 ^ ((ng & 3) << 1);
                #pragma unroll
                for (int j = 0; j < 4; j++) {
                    int n = (ng << 2) + j;
                    if (isLo) BlS[s2][n][sw] = pack_lo2(v0[j], v1[j]);
                    else      BhS[s2][n][sw] = pack_hi2(v0[j], v1[j]);
                }
            }
        }
        __syncthreads();
    }

    #pragma unroll
    for (int mt = 0; mt < 2; mt++) {
        #pragma unroll
        for (int nt = 0; nt < 4; nt++) {
            int col = n0 + (wn << 5) + (nt << 3) + (t << 1);
            float b0 = bias ? bias[col]     : 0.f;
            float b1 = bias ? bias[col + 1] : 0.f;
            #pragma unroll
            for (int half = 0; half < 2; half++) {
                int row = m0 + (wm << 5) + (mt << 4) + g + (half << 3);
                float v0 = acc[mt][nt][half * 2 + 0] + b0;
                float v1 = acc[mt][nt][half * 2 + 1] + b1;
                if (ACT == 1) {
                    v0 = 0.5f * v0 * (1.0f + erff(v0 * 0.70710678118654752f));
                    v1 = 0.5f * v1 * (1.0f + erff(v1 * 0.70710678118654752f));
                }
                *(float2*)(C + (long)row * ldc + col) = make_float2(v0, v1);
            }
        }
    }
}

// ======== 64x64 bf16 tensor-core GEMM (3xBF16, 128 threads, 2x2 warps) ========
// Same warp tile (32x32) and inner loop as bgemm_k; half the M-tile so launches
// that were stuck at 128 blocks get 256+ blocks (latency hiding via occupancy).
template<int ACT, bool TB, int NJ>
__global__ __launch_bounds__(128)
void bgemm64_k(JobsP<NJ> P, int K, int lda, int ldb, int ldc)
{
    const JobDesc jd = P.j[blockIdx.z];
    const int m0 = blockIdx.y << 6;
    if (m0 >= jd.M) return;
    const float* __restrict__ A  = jd.A;
    const float* __restrict__ Bm = jd.B;
    float* __restrict__ C = jd.C;
    const float* bias = jd.bias;
    const int n0 = blockIdx.x << 6;

    __shared__ uint32_t AhS[2][64][12];
    __shared__ uint32_t AlS[2][64][12];
    __shared__ uint32_t BhS[2][64][12];
    __shared__ uint32_t BlS[2][64][12];

    const int tid  = threadIdx.x;
    const int warp = tid >> 5, lane = tid & 31;
    const int wm = warp >> 1;          // 0..1
    const int wn = warp & 1;           // 0..1
    const int g  = lane >> 2;          // 0..7
    const int t  = lane & 3;           // 0..3

    const int ar  = tid >> 1;                // 0..63
    const int acf = (tid & 1) << 3;          // 0 or 8
    const int brn  = tid >> 1;               // 0..63 (TB)
    const int bckf = (tid & 1) << 3;         // 0 or 8 (TB, floats)
    const int ng   = lane & 15;              // !TB n-group
    const int isLo = lane >> 4;

    float acc[2][4][4] = {};
    float4 ra0, ra1, rbA0, rbA1, rbB0, rbB1;

    // ---- prologue loads ----
    {
        const float* Ap = A + (long)(m0 + ar) * lda + acf;
        ra0 = *(const float4*)Ap; ra1 = *(const float4*)(Ap + 4);
        if (TB) {
            const float* Bp = Bm + (long)(n0 + brn) * ldb + bckf;
            rbA0 = *(const float4*)Bp; rbA1 = *(const float4*)(Bp + 4);
        } else {
            int kp0 = warp * 2, kp1 = warp * 2 + 1;
            const float* B0 = Bm + (long)(2 * kp0) * ldb + n0 + (ng << 2);
            rbA0 = *(const float4*)B0; rbA1 = *(const float4*)(B0 + ldb);
            const float* B1 = Bm + (long)(2 * kp1) * ldb + n0 + (ng << 2);
            rbB0 = *(const float4*)B1; rbB1 = *(const float4*)(B1 + ldb);
        }
    }
    // ---- split + store stage 0 ----
    {
        uint4 h4, l4;
        split2(ra0.x, ra0.y, h4.x, l4.x); split2(ra0.z, ra0.w, h4.y, l4.y);
        split2(ra1.x, ra1.y, h4.z, l4.z); split2(ra1.z, ra1.w, h4.w, l4.w);
        *(uint4*)&AhS[0][ar][acf >> 1] = h4;
        *(uint4*)&AlS[0][ar][acf >> 1] = l4;
        if (TB) {
            uint4 bh4, bl4;
            split2(rbA0.x, rbA0.y, bh4.x, bl4.x); split2(rbA0.z, rbA0.w, bh4.y, bl4.y);
            split2(rbA1.x, rbA1.y, bh4.z, bl4.z); split2(rbA1.z, rbA1.w, bh4.w, bl4.w);
            *(uint4*)&BhS[0][brn][bckf >> 1] = bh4;
            *(uint4*)&BlS[0][brn][bckf >> 1] = bl4;
        } else {
            #pragma unroll
            for (int it = 0; it < 2; it++) {
                int kpi = warp * 2 + it;
                int sw = kpi ^ ((ng & 3) << 1);
                float v0[4], v1[4];
                if (it == 0) { v0[0]=rbA0.x; v0[1]=rbA0.y; v0[2]=rbA0.z; v0[3]=rbA0.w;
                               v1[0]=rbA1.x; v1[1]=rbA1.y; v1[2]=rbA1.z; v1[3]=rbA1.w; }
                else         { v0[0]=rbB0.x; v0[1]=rbB0.y; v0[2]=rbB0.z; v0[3]=rbB0.w;
                               v1[0]=rbB1.x; v1[1]=rbB1.y; v1[2]=rbB1.z; v1[3]=rbB1.w; }
                #pragma unroll
                for (int j = 0; j < 4; j++) {
                    int n = (ng << 2) + j;
                    if (isLo) BlS[0][n][sw] = pack_lo2(v0[j], v1[j]);
                    else      BhS[0][n][sw] = pack_hi2(v0[j], v1[j]);
                }
            }
        }
    }
    __syncthreads();

    const int KT = K >> 4;
    for (int kt = 0; kt < KT; kt++) {
        const int s = kt & 1;
        const bool more = (kt + 1 < KT);
        if (more) {
            int kf = (kt + 1) << 4;
            const float* Ap = A + (long)(m0 + ar) * lda + kf + acf;
            ra0 = *(const float4*)Ap; ra1 = *(const float4*)(Ap + 4);
            if (TB) {
                const float* Bp = Bm + (long)(n0 + brn) * ldb + kf + bckf;
                rbA0 = *(const float4*)Bp; rbA1 = *(const float4*)(Bp + 4);
            } else {
                int kp0 = warp * 2, kp1 = warp * 2 + 1;
                const float* B0 = Bm + (long)(kf + 2 * kp0) * ldb + n0 + (ng << 2);
                rbA0 = *(const float4*)B0; rbA1 = *(const float4*)(B0 + ldb);
                const float* B1 = Bm + (long)(kf + 2 * kp1) * ldb + n0 + (ng << 2);
                rbB0 = *(const float4*)B1; rbB1 = *(const float4*)(B1 + ldb);
            }
        }
        {
            uint32_t ah[2][4], al[2][4], bh[4][2], bl[4][2];
            #pragma unroll
            for (int mt = 0; mt < 2; mt++) {
                int mr = (wm << 5) + (mt << 4);
                ah[mt][0] = AhS[s][mr + g][t];
                ah[mt][1] = AhS[s][mr + g + 8][t];
                ah[mt][2] = AhS[s][mr + g][t + 4];
                ah[mt][3] = AhS[s][mr + g + 8][t + 4];
                al[mt][0] = AlS[s][mr + g][t];
                al[mt][1] = AlS[s][mr + g + 8][t];
                al[mt][2] = AlS[s][mr + g][t + 4];
                al[mt][3] = AlS[s][mr + g + 8][t + 4];
            }
            #pragma unroll
            for (int nt = 0; nt < 4; nt++) {
                int nc = (wn << 5) + (nt << 3) + g;
                int idx0 = TB ? t : (t ^ (((nc >> 2) & 3) << 1));
                bh[nt][0] = BhS[s][nc][idx0];
                bh[nt][1] = BhS[s][nc][idx0 ^ 4];
                bl[nt][0] = BlS[s][nc][idx0];
                bl[nt][1] = BlS[s][nc][idx0 ^ 4];
            }
            #pragma unroll
            for (int mt = 0; mt < 2; mt++)
                #pragma unroll
                for (int nt = 0; nt < 4; nt++) mma_bf16(acc[mt][nt], ah[mt], bh[nt]);
            #pragma unroll
            for (int mt = 0; mt < 2; mt++)
                #pragma unroll
                for (int nt = 0; nt < 4; nt++) mma_bf16(acc[mt][nt], ah[mt], bl[nt]);
            #pragma unroll
            for (int mt = 0; mt < 2; mt++)
                #pragma unroll
                for (int nt = 0; nt < 4; nt++) mma_bf16(acc[mt][nt], al[mt], bh[nt]);
        }
        if (more) {
            const int s2 = (kt + 1) & 1;
            uint4 h4, l4;
            split2(ra0.x, ra0.y, h4.x, l4.x); split2(ra0.z, ra0.w, h4.y, l4.y);
            split2(ra1.x, ra1.y, h4.z, l4.z); split2(ra1.z, ra1.w, h4.w, l4.w);
            *(uint4*)&AhS[s2][ar][acf >> 1] = h4;
            *(uint4*)&AlS[s2][ar][acf >> 1] = l4;
            if (TB) {
                uint4 bh4, bl4;
                split2(rbA0.x, rbA0.y, bh4.x, bl4.x); split2(rbA0.z, rbA0.w, bh4.y, bl4.y);
                split2(rbA1.x, rbA1.y, bh4.z, bl4.z); split2(rbA1.z, rbA1.w, bh4.w, bl4.w);
                *(uint4*)&BhS[s2][brn][bckf >> 1] = bh4;
                *(uint4*)&BlS[s2][brn][bckf >> 1] = bl4;
            } else {
                #pragma unroll
                for (int it = 0; it < 2; it++) {
                    int kpi = warp * 2 + it;
                    int sw = kpi ^ ((ng & 3) << 1);
                    float v0[4], v1[4];
                    if (it == 0) { v0[0]=rbA0.x; v0[1]=rbA0.y; v0[2]=rbA0.z; v0[3]=rbA0.w;
                                   v1[0]=rbA1.x; v1[1]=rbA1.y; v1[2]=rbA1.z; v1[3]=rbA1.w; }
                    else         { v0[0]=rbB0.x; v0[1]=rbB0.y; v0[2]=rbB0.z; v0[3]=rbB0.w;
                                   v1[0]=rbB1.x; v1[1]=rbB1.y; v1[2]=rbB1.z; v1[3]=rbB1.w; }
                    #pragma unroll
                    for (int j = 0; j < 4; j++) {
                        int n = (ng << 2) + j;
                        if (isLo) BlS[s2][n][sw] = pack_lo2(v0[j], v1[j]);
                        else      BhS[s2][n][sw] = pack_hi2(v0[j], v1[j]);
                    }
                }
            }
        }
        __syncthreads();
    }

    #pragma unroll
    for (int mt = 0; mt < 2; mt++) {
        #pragma unroll
        for (int nt = 0; nt < 4; nt++) {
            int col = n0 + (wn << 5) + (nt << 3) + (t << 1);
            float b0 = bias ? bias[col]     : 0.f;
            float b1 = bias ? bias[col + 1] : 0.f;
            #pragma unroll
            for (int half = 0; half < 2; half++) {
                int row = m0 + (wm << 5) + (mt << 4) + g + (half << 3);
                float v0 = acc[mt][nt][half * 2 + 0] + b0;
                float v1 = acc[mt][nt][half * 2 + 1] + b1;
                if (ACT == 1) {
                    v0 = 0.5f * v0 * (1.0f + erff(v0 * 0.70710678118654752f));
                    v1 = 0.5f * v1 * (1.0f + erff(v1 * 0.70710678118654752f));
                }
                *(float2*)(C + (long)row * ldc + col) = make_float2(v0, v1);
            }
        }
    }
}

// ---------------- embedding: x = LN(word_emb[id]) * maskf ---------------------
__global__ void embed_ln_k(const float* __restrict__ emb,
                           const float* __restrict__ s, const float* __restrict__ b,
                           const int* __restrict__ ids, const int* __restrict__ am,
                           float* __restrict__ out)
{
    __shared__ float sh[HID];
    __shared__ float red[8];
    int tok = blockIdx.x;
    long ebase = (long)ids[tok] * HID;
    float m = (float)am[tok];
    float ls = 0.f;
    for (int i = threadIdx.x; i < HID; i += blockDim.x) { float v = emb[ebase + i]; sh[i] = v; ls += v; }
    __syncthreads();
    float mu = blk_sum(ls, red) * (1.0f / HID);
    float lv = 0.f;
    for (int i = threadIdx.x; i < HID; i += blockDim.x) { float d = sh[i] - mu; lv += d * d; }
    float var = blk_sum(lv, red) * (1.0f / HID);
    float r = rsqrtf(var + 1e-7f);
    long obase = (long)tok * HID;
    for (int i = threadIdx.x; i < HID; i += blockDim.x)
        out[obase + i] = ((sh[i] - mu) * r * s[i] + b[i]) * m;
}

// ---------------- residual + LN -----------------------------------------------
__global__ void add_ln_k(const float* res, const float* __restrict__ t,
                         const float* __restrict__ s, const float* __restrict__ b,
                         float* out)
{
    __shared__ float sh[HID];
    __shared__ float red[8];
    long base = (long)blockIdx.x * HID;
    float ls = 0.f;
    for (int i = threadIdx.x; i < HID; i += blockDim.x) {
        float v = t[base + i];
        if (res) v += res[base + i];
        sh[i] = v; ls += v;
    }
    __syncthreads();
    float mu = blk_sum(ls, red) * (1.0f / HID);
    float lv = 0.f;
    for (int i = threadIdx.x; i < HID; i += blockDim.x) { float d = sh[i] - mu; lv += d * d; }
    float var = blk_sum(lv, red) * (1.0f / HID);
    float r = rsqrtf(var + 1e-7f);
    for (int i = threadIdx.x; i < HID; i += blockDim.x)
        out[base + i] = (sh[i] - mu) * r * s[i] + b[i];
}

// ---------------- DeBERTa log-bucket relative index ---------------------------
__global__ void build_idx_k(int* __restrict__ idxm)
{
    int q = blockIdx.x;
    const int mid = 128;
    for (int k = threadIdx.x; k < SEQ; k += blockDim.x) {
        int rel = q - k;
        int a = (rel < mid && rel > -mid) ? (mid - 1) : (rel < 0 ? -rel : rel);
        int bucket;
        if (a <= mid) bucket = rel;
        else {
            float lp = ceilf(logf((float)a / (float)mid) / logf(511.0f / (float)mid) * (float)(mid - 1))
                       + (float)mid;
            float sgn = (rel > 0) ? 1.f : ((rel < 0) ? -1.f : 0.f);
            bucket = (int)(lp * sgn);
        }
        int J = bucket + 256;
        J = J < 0 ? 0 : (J > 511 ? 511 : J);
        idxm[q * SEQ + k] = J;
    }
}

// ------- combine + mask + softmax ---------------------------------------------
__global__ void attn_softmax_k(float* __restrict__ sc, const float* __restrict__ c2p,
                               const float* __restrict__ p2c, const int* __restrict__ idxm,
                               const int* __restrict__ am)
{
    __shared__ float red[4];
    int q = blockIdx.x, z = blockIdx.y;
    int b = z >> 4;
    long ro = ((long)z * SEQ + q) * (long)SEQ;
    float* row = sc + ro;
    const float* cr = c2p + ro;
    const float* pb = p2c + (long)z * SEQ * 512;
    int mq = am[b * SEQ + q];
    const float scale = sqrtf(3.0f * (float)HDD);
    float vals[4]; int msk[4];
    float mx = -3.402823466e38f;
    #pragma unroll
    for (int t = 0; t < 4; t++) {
        int k = threadIdx.x + t * 128;
        int J = idxm[q * SEQ + k];
        float v = (row[k] + cr[J] + pb[(long)k * 512 + J]) / scale;
        int mk = mq & am[b * SEQ + k];
        vals[t] = v; msk[t] = mk;
        if (mk) mx = fmaxf(mx, v);
    }
    #pragma unroll
    for (int o = 16; o; o >>= 1) mx = fmaxf(mx, __shfl_down_sync(0xffffffffu, mx, o));
    if ((threadIdx.x & 31) == 0) red[threadIdx.x >> 5] = mx;
    __syncthreads();
    mx = fmaxf(fmaxf(red[0], red[1]), fmaxf(red[2], red[3]));
    float ls = 0.f;
    #pragma unroll
    for (int t = 0; t < 4; t++) {
        float e = msk[t] ? expf(vals[t] - mx) : 0.f;
        vals[t] = e; ls += e;
    }
    __syncthreads();
    #pragma unroll
    for (int o = 16; o; o >>= 1) ls += __shfl_down_sync(0xffffffffu, ls, o);
    if ((threadIdx.x & 31) == 0) red[threadIdx.x >> 5] = ls;
    __syncthreads();
    float sum = red[0] + red[1] + red[2] + red[3];
    float inv = sum > 0.f ? 1.0f / sum : 0.f;
    #pragma unroll
    for (int t = 0; t < 4; t++) row[threadIdx.x + t * 128] = vals[t] * inv;
}

// ---------------- decoder (N=14) + per-row masked NLL -------------------------
__global__ void decoder_k(const float* __restrict__ t, const float* __restrict__ Wd,
                          const float* __restrict__ bd, const int* __restrict__ labels,
                          const int* __restrict__ am, float* __restrict__ out,
                          int logit_limit, float* __restrict__ nll)
{
    __shared__ float sh[HID];
    __shared__ float wred[4][NCL];
    __shared__ float lg[NCL];
    int row = blockIdx.x;
    long base = (long)row * HID;
    for (int i = threadIdx.x; i < HID; i += 128) sh[i] = t[base + i];
    __syncthreads();
    float p[NCL];
    #pragma unroll
    for (int c = 0; c < NCL; c++) p[c] = 0.f;
    for (int i = threadIdx.x; i < HID; i += 128) {
        float tv = sh[i];
        const float* w = Wd + (long)i * NCL;
        #pragma unroll
        for (int c = 0; c < NCL; c++) p[c] = fmaf(tv, w[c], p[c]);
    }
    #pragma unroll
    for (int c = 0; c < NCL; c++)
        #pragma unroll
        for (int o = 16; o; o >>= 1) p[c] += __shfl_down_sync(0xffffffffu, p[c], o);
    if ((threadIdx.x & 31) == 0) {
        int w = threadIdx.x >> 5;
        #pragma unroll
        for (int c = 0; c < NCL; c++) wred[w][c] = p[c];
    }
    __syncthreads();
    if (threadIdx.x < NCL) {
        float v = wred[0][threadIdx.x] + wred[1][threadIdx.x]
                + wred[2][threadIdx.x] + wred[3][threadIdx.x] + bd[threadIdx.x];
        lg[threadIdx.x] = v;
        int oi = row * NCL + threadIdx.x;
        if (oi < logit_limit) out[oi] = v;
    }
    __syncthreads();
    if (threadIdx.x == 0) {
        float m = lg[0];
        #pragma unroll
        for (int c = 1; c < NCL; c++) m = fmaxf(m, lg[c]);
        float ssum = 0.f;
        #pragma unroll
        for (int c = 0; c < NCL; c++) ssum += expf(lg[c] - m);
        float lse = m + logf(ssum);
        float nl = lse - lg[labels[row]];
        nll[row] = nl * (float)am[row];
    }
}

__global__ void finalize_k(const float* __restrict__ nll, const int* __restrict__ am,
                           float* __restrict__ out, int loss_idx)
{
    __shared__ float red[8];
    float a = 0.f, bm = 0.f;
    for (int i = threadIdx.x; i < TOK; i += 256) { a += nll[i]; bm += (float)am[i]; }
    float sa = blk_sum(a, red);
    float sb = blk_sum(bm, red);
    if (threadIdx.x == 0 && loss_idx >= 0) out[loss_idx] = sa / fmaxf(sb, 1.0f);
}

// ------------------------------- host driver ----------------------------------
static inline JobDesc mkjob(const float* A, const float* B, float* C,
                            const float* bias, int M)
{
    JobDesc d; d.A = A; d.B = B; d.C = C; d.bias = bias; d.M = M; d.pad = 0;
    return d;
}

extern "C" void kernel_launch(void* const* d_in, const int* in_sizes, int n_in,
                              void* d_out, int out_size)
{
    (void)in_sizes; (void)n_in;
    const float* word_emb = (const float*)d_in[0];
    const float* emb_ln_s = (const float*)d_in[1];
    const float* emb_ln_b = (const float*)d_in[2];
    const float* rel_emb  = (const float*)d_in[3];
    const float* rel_ln_s = (const float*)d_in[4];
    const float* rel_ln_b = (const float*)d_in[5];
    const float* Wq = (const float*)d_in[6];
    const float* bq = (const float*)d_in[7];
    const float* Wk = (const float*)d_in[8];
    const float* bk = (const float*)d_in[9];
    const float* Wv = (const float*)d_in[10];
    const float* bv = (const float*)d_in[11];
    const float* Wo = (const float*)d_in[12];
    const float* bo = (const float*)d_in[13];
    const float* ln1_s = (const float*)d_in[14];
    const float* ln1_b = (const float*)d_in[15];
    const float* W1 = (const float*)d_in[16];
    const float* b1 = (const float*)d_in[17];
    const float* W2 = (const float*)d_in[18];
    const float* b2 = (const float*)d_in[19];
    const float* ln2_s = (const float*)d_in[20];
    const float* ln2_b = (const float*)d_in[21];
    const float* Wt = (const float*)d_in[22];
    const float* bt = (const float*)d_in[23];
    const float* tln_s = (const float*)d_in[24];
    const float* tln_b = (const float*)d_in[25];
    const float* Wd = (const float*)d_in[26];
    const float* bd = (const float*)d_in[27];
    const int* ids    = (const int*)d_in[28];
    const int* am     = (const int*)d_in[29];
    const int* labels = (const int*)d_in[30];
    float* out = (float*)d_out;

    float *x, *q, *k, *v, *rel, *pk, *pq, *sc, *c2p, *p2c, *ctx, *ff, *nll;
    int* idxm;
    cudaGetSymbolAddress((void**)&x,   g_x);
    cudaGetSymbolAddress((void**)&q,   g_q);
    cudaGetSymbolAddress((void**)&k,   g_k);
    cudaGetSymbolAddress((void**)&v,   g_v);
    cudaGetSymbolAddress((void**)&rel, g_rel);
    cudaGetSymbolAddress((void**)&pk,  g_pk);
    cudaGetSymbolAddress((void**)&pq,  g_pq);
    cudaGetSymbolAddress((void**)&sc,  g_sc);
    cudaGetSymbolAddress((void**)&c2p, g_c2p);
    cudaGetSymbolAddress((void**)&p2c, g_p2c);
    cudaGetSymbolAddress((void**)&ctx, g_ctx);
    cudaGetSymbolAddress((void**)&ff,  g_ff);
    cudaGetSymbolAddress((void**)&nll, g_nll);
    cudaGetSymbolAddress((void**)&idxm, g_idxm);

    build_idx_k<<<SEQ, 128>>>(idxm);
    embed_ln_k<<<TOK, 256>>>(word_emb, emb_ln_s, emb_ln_b, ids, am, x);
    add_ln_k<<<SEQ, 256>>>(nullptr, rel_emb, rel_ln_s, rel_ln_b, rel);

    // -- fixed job tables (same scratch addresses every layer) --
    JobsP<96> scJobs;
    for (int job = 0; job < 3; job++)
        for (int head = 0; head < 32; head++) {
            int b = head >> 4, h = head & 15;
            const float* Aj = (job < 2 ? q : k) + (long)b * SHs + h * HDD;
            const float* Bj;
            if (job == 0)      Bj = k  + (long)b * SHs + h * HDD;
            else if (job == 1) Bj = pk + h * HDD;
            else               Bj = pq + h * HDD;
            float* Cj = (job == 0 ? sc : job == 1 ? c2p : p2c) + (long)head * HSC;
            scJobs.j[job * 32 + head] = mkjob(Aj, Bj, Cj, nullptr, 512);
        }
    JobsP<32> ctxJobs;
    for (int head = 0; head < 32; head++) {
        int b = head >> 4, h = head & 15;
        ctxJobs.j[head] = mkjob(sc + (long)head * HSC,
                                v + (long)b * SHs + h * HDD,
                                ctx + (long)b * SHs + h * HDD, nullptr, 512);
    }

    for (int l = 0; l < NL; l++) {
        const float* Wq_l = Wq + (long)l * HID * HID;
        const float* Wk_l = Wk + (long)l * HID * HID;
        const float* Wv_l = Wv + (long)l * HID * HID;
        const float* Wo_l = Wo + (long)l * HID * HID;
        const float* bq_l = bq + l * HID;
        const float* bk_l = bk + l * HID;
        const float* bv_l = bv + l * HID;
        const float* bo_l = bo + l * HID;
        const float* W1_l = W1 + (long)l * HID * FFD;
        const float* b1_l = b1 + l * FFD;
        const float* W2_l = W2 + (long)l * FFD * HID;
        const float* b2_l = b2 + l * HID;

        // fused Q/K/V projections + positional K/Q (share_att_key) — 640 blocks
        JobsP<8> pj;
        pj.j[0] = mkjob(x,   Wq_l, q,  bq_l, 1024);
        pj.j[1] = mkjob(x,   Wk_l, k,  bk_l, 1024);
        pj.j[2] = mkjob(x,   Wv_l, v,  bv_l, 1024);
        pj.j[3] = mkjob(rel, Wk_l, pk, bk_l, 512);
        pj.j[4] = mkjob(rel, Wq_l, pq, bq_l, 512);
        bgemm_k<0,false,8><<<dim3(16,8,5), 256>>>(pj, HID, HID, HID, HID);

        // fused attention GEMMs: qk, c2p, p2c — 3072 blocks
        bgemm_k<0,true,96><<<dim3(8,4,96), 256>>>(scJobs, HDD, HID, HID, 512);

        // combine disentangled biases + mask + softmax
        attn_softmax_k<<<dim3(SEQ, BSZ * NHD), 128>>>(sc, c2p, p2c, idxm, am);

        // ctx = probs @ V (per head, N=64) — 64-row tiles: 256 blocks
        bgemm64_k<0,false,32><<<dim3(1,8,32), 128>>>(ctxJobs, SEQ, 512, HID, HID);

        // output proj — 64-row tiles: 256 blocks
        JobsP<8> oj; oj.j[0] = mkjob(ctx, Wo_l, ff, bo_l, 1024);
        bgemm64_k<0,false,8><<<dim3(16,16,1), 128>>>(oj, HID, HID, HID, HID);
        add_ln_k<<<TOK, 256>>>(x, ff, ln1_s + l * HID, ln1_b + l * HID, x);

        // FFN: FF1 512 blocks (keep 128-tile); FF2 64-row tiles: 256 blocks
        JobsP<8> f1; f1.j[0] = mkjob(x, W1_l, ff, b1_l, 1024);
        bgemm_k<1,false,8><<<dim3(64,8,1), 256>>>(f1, HID, HID, FFD, FFD);
        JobsP<8> f2; f2.j[0] = mkjob(ff, W2_l, ctx, b2_l, 1024);
        bgemm64_k<0,false,8><<<dim3(16,16,1), 128>>>(f2, FFD, FFD, HID, HID);
        add_ln_k<<<TOK, 256>>>(x, ctx, ln2_s + l * HID, ln2_b + l * HID, x);
    }

    // transform head: LN(gelu(x @ Wt + bt)) — 64-row tiles: 256 blocks
    JobsP<8> tj; tj.j[0] = mkjob(x, Wt, ff, bt, 1024);
    bgemm64_k<1,false,8><<<dim3(16,16,1), 128>>>(tj, HID, HID, HID, HID);
    add_ln_k<<<TOK, 256>>>(nullptr, ff, tln_s, tln_b, q);   // reuse q buffer as t

    int logits_n = TOK * NCL;                               // 14336
    int logit_limit = (out_size > 1) ? (out_size < logits_n ? out_size : logits_n) : 0;
    int loss_idx = (out_size == 1) ? 0 : (out_size > logits_n ? logits_n : -1);
    decoder_k<<<TOK, 128>>>(q, Wd, bd, labels, am, out, logit_limit, nll);
    finalize_k<<<1, 256>>>(nll, am, out, loss_idx);
}